// round 9
// baseline (speedup 1.0000x reference)
#include <cuda_runtime.h>
#include <cuda_bf16.h>
#include <math.h>
#include <stdint.h>

#define NTOK 8192
#define DIM  1024
#define FFN  4096
#define NE   10

typedef __nv_bfloat16 bf16;

// ---------------- scratch (device globals: no allocation allowed) ----------
__device__ bf16  g_Ab [(size_t)NTOK * FFN];   // shared gelu acts (token rows)
__device__ bf16  g_Ad [(size_t)NTOK * FFN];   // domain gelu acts (perm rows)
__device__ float g_H  [(size_t)NTOK * DIM];   // shared h
__device__ float g_Hd [(size_t)NTOK * DIM];   // domain h (perm rows)
__device__ float g_Xg [(size_t)NTOK * DIM];   // gathered x fp32 (perm rows)
__device__ bf16  g_Xb [(size_t)NTOK * DIM];   // x bf16 (token rows)
__device__ bf16  g_Xgb[(size_t)NTOK * DIM];   // gathered x bf16 (perm rows)
__device__ int   g_perm[NTOK];
__device__ int   g_cnt[NE];
__device__ int   g_off[NE];
__device__ int   g_cur[NE];
__device__ int   g_tileTab[80];
__device__ int   g_ntile;

// transposed bf16 weights: Wt[n*K + k] = bf16(W[k*N + n])
__device__ bf16 g_sW1t[(size_t)FFN * DIM];
__device__ bf16 g_sW2t[(size_t)DIM * FFN];
__device__ bf16 g_sWgt[(size_t)DIM * DIM];
__device__ bf16 g_dW1t[(size_t)NE * FFN * DIM];
__device__ bf16 g_dW2t[(size_t)NE * DIM * FFN];
__device__ bf16 g_dWgt[(size_t)NE * DIM * DIM];

// ---------------- PTX helpers ------------------------------------------------
__device__ __forceinline__ uint32_t smem_u32(const void* p) {
    uint32_t a;
    asm("{ .reg .u64 t; cvta.to.shared.u64 t, %1; cvt.u32.u64 %0, t; }" : "=r"(a) : "l"(p));
    return a;
}
__device__ __forceinline__ void cp16(uint32_t dst, const void* src, int srcbytes) {
    asm volatile("cp.async.cg.shared.global [%0], [%1], 16, %2;"
                 :: "r"(dst), "l"(src), "r"(srcbytes) : "memory");
}
__device__ __forceinline__ void cp_commit() {
    asm volatile("cp.async.commit_group;" ::: "memory");
}
template <int N>
__device__ __forceinline__ void cp_wait() {
    asm volatile("cp.async.wait_group %0;" :: "n"(N) : "memory");
}
__device__ __forceinline__ void ldsm_x4(uint32_t* r, uint32_t addr) {
    asm volatile("ldmatrix.sync.aligned.m8n8.x4.shared.b16 {%0,%1,%2,%3}, [%4];"
                 : "=r"(r[0]), "=r"(r[1]), "=r"(r[2]), "=r"(r[3]) : "r"(addr));
}
__device__ __forceinline__ void ldsm_x2(uint32_t* r, uint32_t addr) {
    asm volatile("ldmatrix.sync.aligned.m8n8.x2.shared.b16 {%0,%1}, [%2];"
                 : "=r"(r[0]), "=r"(r[1]) : "r"(addr));
}
__device__ __forceinline__ void mma_bf16(float* c, const uint32_t* a, const uint32_t* b) {
    asm volatile(
        "mma.sync.aligned.m16n8k16.row.col.f32.bf16.bf16.f32 "
        "{%0,%1,%2,%3},{%4,%5,%6,%7},{%8,%9},{%0,%1,%2,%3};"
        : "+f"(c[0]), "+f"(c[1]), "+f"(c[2]), "+f"(c[3])
        : "r"(a[0]), "r"(a[1]), "r"(a[2]), "r"(a[3]), "r"(b[0]), "r"(b[1]));
}

// ---------------- routing ---------------------------------------------------
__global__ void k_zero() {
    int i = threadIdx.x;
    if (i < NE) { g_cnt[i] = 0; g_cur[i] = 0; }
}
__global__ void k_count(const int* __restrict__ ids) {
    int i = blockIdx.x * blockDim.x + threadIdx.x;
    if (i < NTOK) atomicAdd(&g_cnt[ids[i]], 1);
}
__global__ void k_scan() {
    if (threadIdx.x == 0) {
        int s = 0;
        for (int e = 0; e < NE; e++) { g_off[e] = s; s += g_cnt[e]; }
        int t = 0;
        for (int e = 0; e < NE; e++) {
            int nt = (g_cnt[e] + 127) >> 7;
            for (int q = 0; q < nt; q++) g_tileTab[t++] = (e << 16) | q;
        }
        g_ntile = t;
    }
}
__global__ void k_scatter(const int* __restrict__ ids) {
    int i = blockIdx.x * blockDim.x + threadIdx.x;
    if (i < NTOK) {
        int e = ids[i];
        int p = g_off[e] + atomicAdd(&g_cur[e], 1);
        g_perm[p] = i;
    }
}
__global__ void k_gather(const float* __restrict__ x) {
    int p   = blockIdx.x;
    int src = g_perm[p];
    float4 v = ((const float4*)(x + (size_t)src * DIM))[threadIdx.x];
    ((float4*)(g_Xg + (size_t)p * DIM))[threadIdx.x] = v;
    union { __nv_bfloat162 h; uint32_t u; } a, b;
    a.h = __floats2bfloat162_rn(v.x, v.y);
    b.h = __floats2bfloat162_rn(v.z, v.w);
    ((uint2*)(g_Xgb + (size_t)p * DIM))[threadIdx.x] = make_uint2(a.u, b.u);
}

// ---------------- converts ---------------------------------------------------
__global__ void k_cvt_x(const float* __restrict__ x) {
    int i = blockIdx.x * blockDim.x + threadIdx.x;
    float4 v = ((const float4*)x)[i];
    union { __nv_bfloat162 h; uint32_t u; } a, b;
    a.h = __floats2bfloat162_rn(v.x, v.y);
    b.h = __floats2bfloat162_rn(v.z, v.w);
    ((uint2*)g_Xb)[i] = make_uint2(a.u, b.u);
}
__global__ void k_transpose(const float* __restrict__ W, int K, int N, int which) {
    bf16* Wt = which == 0 ? g_sW1t : which == 1 ? g_sW2t : which == 2 ? g_sWgt
             : which == 3 ? g_dW1t : which == 4 ? g_dW2t : g_dWgt;
    int e = blockIdx.z;
    W  += (size_t)e * K * N;
    Wt += (size_t)e * K * N;
    __shared__ float t[32][33];
    int n0 = blockIdx.x * 32, k0 = blockIdx.y * 32;
#pragma unroll
    for (int i = threadIdx.y; i < 32; i += 8)
        t[i][threadIdx.x] = W[(size_t)(k0 + i) * N + n0 + threadIdx.x];
    __syncthreads();
#pragma unroll
    for (int i = threadIdx.y; i < 32; i += 8)
        Wt[(size_t)(n0 + i) * K + k0 + threadIdx.x] = __float2bfloat16(t[threadIdx.x][i]);
}

// ---------------- tiling -----------------------------------------------------
// BM=128, BN=256, BK=64, 512 threads (16 warps 2x8), warp tile 64x32.
// 3-stage cp.async pipeline, one __syncthreads per K-chunk.
#define ROWB   144                         // staged row stride bytes (128 payload + 16)
#define ABUF   (128 * ROWB)                // A bytes per stage (18432)
#define BBUF   (256 * ROWB)                // B bytes per stage (36864)
#define STAGES 3
#define SMEM_BYTES (STAGES * (ABUF + BBUF))   // 165888

// resolve (shared|domain) tile coords; false -> CTA exits
__device__ __forceinline__ bool tile_coords(int by, int domSel, bool& dom, int& e,
                                            int& Mloc, int& rowBase, int& rowTile) {
    if (domSel < 0) { dom = by >= 64; if (dom) by -= 64; }
    else            dom = domSel != 0;
    if (!dom) {
        e = 0; Mloc = NTOK; rowBase = 0; rowTile = by * 128;
    } else {
        if (by >= g_ntile) return false;
        int pk  = g_tileTab[by];
        e       = pk >> 16;
        rowTile = (pk & 0xffff) * 128;
        Mloc    = g_cnt[e];
        rowBase = g_off[e];
    }
    return true;
}

// MODE 0: acts = bf16(gelu(x@W1+b1));  MODE 1: h = A@W2+b2+x;  MODE 2: gate+mix
template <int MODE>
__global__ void __launch_bounds__(512, 1) gemm_bf(
    const float* __restrict__ xf,
    const float* __restrict__ sbias, const float* __restrict__ dbias,
    float* __restrict__ Fout, int K, int Nd, int domSel)
{
    bool dom; int e, Mloc, rowBase, rowTile;
    if (!tile_coords(blockIdx.y, domSel, dom, e, Mloc, rowBase, rowTile)) return;

    const bf16* A;
    if (MODE == 1) A = (dom ? g_Ad : g_Ab) + (dom ? (size_t)rowBase * K : 0);
    else           A = dom ? g_Xgb + (size_t)rowBase * K : g_Xb;
    const bf16* Wt =
        MODE == 0 ? (dom ? g_dW1t + (size_t)e * K * Nd : g_sW1t)
      : MODE == 1 ? (dom ? g_dW2t + (size_t)e * K * Nd : g_sW2t)
                  : (dom ? g_dWgt + (size_t)e * K * Nd : g_sWgt);
    const float* bias = dom ? dbias + (size_t)e * Nd : sbias;
    const float* Xr   = dom ? g_Xg : xf;

    extern __shared__ uint8_t sm[];
    uint32_t asb = smem_u32(sm);
    uint32_t bsb = asb + STAGES * ABUF;

    int tid   = threadIdx.x;
    int lane  = tid & 31;
    int warp  = tid >> 5;
    int warpM = warp >> 3;         // 0..1
    int warpN = warp & 7;          // 0..7
    int colTile = blockIdx.x * 256;

    // staging maps (512 threads)
    int arow = tid >> 2;           // 0..127
    int aseg = (tid & 3) * 16;     // elems; 2 cp16 at +0, +8
    int brow = tid >> 1;           // 0..255
    int bseg = (tid & 1) * 32;     // elems; 4 cp16 at +0,8,16,24

    int aoffB = (lane & 15) * ROWB + ((lane >> 4) << 4);
    int boffB = (lane & 7)  * ROWB + (((lane >> 3) & 1) << 4);

    float acc[4][4][4];
#pragma unroll
    for (int mi = 0; mi < 4; mi++)
#pragma unroll
        for (int ni = 0; ni < 4; ni++)
#pragma unroll
            for (int j = 0; j < 4; j++) acc[mi][ni][j] = 0.f;

    const int chunks = K >> 6;

#define ISSUE(chunk, slot)                                                        \
    do {                                                                          \
        int _kk = (chunk) << 6;                                                   \
        uint32_t _aO = asb + (uint32_t)(slot) * ABUF;                             \
        uint32_t _bO = bsb + (uint32_t)(slot) * BBUF;                             \
        int _av = (rowTile + arow) < Mloc ? 16 : 0;                               \
        const bf16* _as = A + (size_t)(rowTile + arow) * K + _kk + aseg;          \
        uint32_t _ad = _aO + (uint32_t)(arow * ROWB + aseg * 2);                  \
        cp16(_ad,      _as,     _av);                                             \
        cp16(_ad + 16, _as + 8, _av);                                             \
        const bf16* _bs = Wt + (size_t)(colTile + brow) * K + _kk + bseg;         \
        uint32_t _bd = _bO + (uint32_t)(brow * ROWB + bseg * 2);                  \
        cp16(_bd,      _bs,      16);                                             \
        cp16(_bd + 16, _bs + 8,  16);                                             \
        cp16(_bd + 32, _bs + 16, 16);                                             \
        cp16(_bd + 48, _bs + 24, 16);                                             \
        cp_commit();                                                              \
    } while (0)

    ISSUE(0, 0);
    ISSUE(1, 1);

    int sCur = 0;
    for (int i = 0; i < chunks; i++) {
        if (i + 1 < chunks) cp_wait<1>();
        else                cp_wait<0>();
        __syncthreads();
        if (i + 2 < chunks) {
            int slot = sCur + 2; if (slot >= STAGES) slot -= STAGES;
            ISSUE(i + 2, slot);
        }
        uint32_t aBuf = asb + (uint32_t)sCur * ABUF;
        uint32_t bBuf = bsb + (uint32_t)sCur * BBUF;
#pragma unroll
        for (int kb = 0; kb < 64; kb += 16) {
            uint32_t af[4][4], bfr[4][2];
#pragma unroll
            for (int mi = 0; mi < 4; mi++)
                ldsm_x4(af[mi], aBuf + (uint32_t)((warpM * 64 + mi * 16) * ROWB + kb * 2 + aoffB));
#pragma unroll
            for (int ni = 0; ni < 4; ni++)
                ldsm_x2(bfr[ni], bBuf + (uint32_t)((warpN * 32 + ni * 8) * ROWB + kb * 2 + boffB));
#pragma unroll
            for (int mi = 0; mi < 4; mi++)
#pragma unroll
                for (int ni = 0; ni < 4; ni++)
                    mma_bf16(acc[mi][ni], af[mi], bfr[ni]);
        }
        if (++sCur == STAGES) sCur = 0;
    }
#undef ISSUE

    // ---------------- epilogue ----------------
    int grp = lane >> 2, t4 = lane & 3;
#pragma unroll
    for (int mi = 0; mi < 4; mi++)
#pragma unroll
        for (int h = 0; h < 2; h++) {
            int lr = rowTile + warpM * 64 + mi * 16 + grp + h * 8;
            if (lr >= Mloc) continue;
            int grow = dom ? rowBase + lr : lr;
#pragma unroll
            for (int ni = 0; ni < 4; ni++) {
                int col = colTile + warpN * 32 + ni * 8 + t4 * 2;
                float v0 = acc[mi][ni][h * 2 + 0];
                float v1 = acc[mi][ni][h * 2 + 1];
                if (MODE == 0) {
                    float a0 = v0 + bias[col];
                    float a1 = v1 + bias[col + 1];
                    a0 = 0.5f * a0 * (1.0f + erff(a0 * 0.70710678118654752f));
                    a1 = 0.5f * a1 * (1.0f + erff(a1 * 0.70710678118654752f));
                    union { __nv_bfloat162 h2; uint32_t u; } cv;
                    cv.h2 = __floats2bfloat162_rn(a0, a1);
                    *(uint32_t*)((dom ? g_Ad : g_Ab) + (size_t)grow * Nd + col) = cv.u;
                } else if (MODE == 1) {
                    float*       dst = (dom ? g_Hd : g_H) + (size_t)grow * Nd + col;
                    const float* r   = Xr + (size_t)grow * Nd + col;
                    dst[0] = v0 + bias[col]     + r[0];
                    dst[1] = v1 + bias[col + 1] + r[1];
                } else {
                    const float* hp = (dom ? g_Hd : g_H) + (size_t)grow * Nd + col;
                    const float* xp = Xr + (size_t)grow * Nd + col;
                    int orow = dom ? g_perm[grow] : grow;
                    float* dst = Fout + (size_t)orow * Nd + col;
                    float g0 = 1.0f / (1.0f + expf(-(v0 + bias[col])));
                    float g1 = 1.0f / (1.0f + expf(-(v1 + bias[col + 1])));
                    float o0 = g0 * hp[0] + (1.0f - g0) * xp[0];
                    float o1 = g1 * hp[1] + (1.0f - g1) * xp[1];
                    if (dom) { dst[0] += o0; dst[1] += o1; }
                    else     { dst[0]  = o0; dst[1]  = o1; }
                }
            }
        }
}

// ---------------- launch -----------------------------------------------------
extern "C" void kernel_launch(void* const* d_in, const int* in_sizes, int n_in,
                              void* d_out, int out_size)
{
    const float* x   = (const float*)d_in[0];
    const int*   ids = (const int*)  d_in[1];
    const float* sW1 = (const float*)d_in[2];
    const float* sb1 = (const float*)d_in[3];
    const float* sW2 = (const float*)d_in[4];
    const float* sb2 = (const float*)d_in[5];
    const float* sWg = (const float*)d_in[6];
    const float* sbg = (const float*)d_in[7];
    const float* dW1 = (const float*)d_in[8];
    const float* db1 = (const float*)d_in[9];
    const float* dW2 = (const float*)d_in[10];
    const float* db2 = (const float*)d_in[11];
    const float* dWg = (const float*)d_in[12];
    const float* dbg = (const float*)d_in[13];
    float* out = (float*)d_out;

    cudaFuncSetAttribute(gemm_bf<0>, cudaFuncAttributeMaxDynamicSharedMemorySize, SMEM_BYTES);
    cudaFuncSetAttribute(gemm_bf<1>, cudaFuncAttributeMaxDynamicSharedMemorySize, SMEM_BYTES);
    cudaFuncSetAttribute(gemm_bf<2>, cudaFuncAttributeMaxDynamicSharedMemorySize, SMEM_BYTES);

    // routing + converts
    k_zero   <<<1, 32>>>();
    k_count  <<<NTOK / 256, 256>>>(ids);
    k_scan   <<<1, 32>>>();
    k_scatter<<<NTOK / 256, 256>>>(ids);
    k_gather <<<NTOK, 256>>>(x);
    k_cvt_x  <<<NTOK * DIM / 4 / 256, 256>>>(x);

    dim3 tb(32, 8);
    k_transpose<<<dim3(FFN / 32, DIM / 32, 1),  tb>>>(sW1, DIM, FFN, 0);
    k_transpose<<<dim3(DIM / 32, FFN / 32, 1),  tb>>>(sW2, FFN, DIM, 1);
    k_transpose<<<dim3(DIM / 32, DIM / 32, 1),  tb>>>(sWg, DIM, DIM, 2);
    k_transpose<<<dim3(FFN / 32, DIM / 32, NE), tb>>>(dW1, DIM, FFN, 3);
    k_transpose<<<dim3(DIM / 32, FFN / 32, NE), tb>>>(dW2, FFN, DIM, 4);
    k_transpose<<<dim3(DIM / 32, DIM / 32, NE), tb>>>(dWg, DIM, DIM, 5);

    // GEMM1 merged (shared gridY 0..63, domain 64..137), BN=256 -> gridX 16
    gemm_bf<0><<<dim3(FFN / 256, 138), 512, SMEM_BYTES>>>(x, sb1, db1, nullptr, DIM, FFN, -1);
    // GEMM2 merged, gridX 4
    gemm_bf<1><<<dim3(DIM / 256, 138), 512, SMEM_BYTES>>>(x, sb2, db2, nullptr, FFN, DIM, -1);
    // GEMM3 gate+mix: shared store first, then domain accumulate (ordering!)
    gemm_bf<2><<<dim3(DIM / 256, 64), 512, SMEM_BYTES>>>(x, sbg, dbg, out, DIM, DIM, 0);
    gemm_bf<2><<<dim3(DIM / 256, 74), 512, SMEM_BYTES>>>(x, sbg, dbg, out, DIM, DIM, 1);
}

// round 10
// speedup vs baseline: 1.2665x; 1.2665x over previous
#include <cuda_runtime.h>
#include <cuda_bf16.h>
#include <math.h>
#include <stdint.h>

#define NTOK 8192
#define DIM  1024
#define FFN  4096
#define NE   10

typedef __nv_bfloat16 bf16;

// ---------------- scratch (device globals: no allocation allowed) ----------
__device__ bf16  g_Ab [(size_t)NTOK * FFN];   // shared gelu acts (token rows)
__device__ bf16  g_Ad [(size_t)NTOK * FFN];   // domain gelu acts (perm rows)
__device__ float g_H  [(size_t)NTOK * DIM];   // shared h
__device__ float g_Hd [(size_t)NTOK * DIM];   // domain h (perm rows)
__device__ float g_Xg [(size_t)NTOK * DIM];   // gathered x fp32 (perm rows)
__device__ bf16  g_Xb [(size_t)NTOK * DIM];   // x bf16 (token rows)
__device__ bf16  g_Xgb[(size_t)NTOK * DIM];   // gathered x bf16 (perm rows)
__device__ int   g_perm[NTOK];
__device__ int   g_cnt[NE];
__device__ int   g_off[NE];
__device__ int   g_cur[NE];
__device__ int   g_tileTab[80];
__device__ int   g_ntile;

// transposed bf16 weights: Wt[n*K + k] = bf16(W[k*N + n])
__device__ bf16 g_sW1t[(size_t)FFN * DIM];
__device__ bf16 g_sW2t[(size_t)DIM * FFN];
__device__ bf16 g_sWgt[(size_t)DIM * DIM];
__device__ bf16 g_dW1t[(size_t)NE * FFN * DIM];
__device__ bf16 g_dW2t[(size_t)NE * DIM * FFN];
__device__ bf16 g_dWgt[(size_t)NE * DIM * DIM];

// ---------------- PTX helpers ------------------------------------------------
__device__ __forceinline__ uint32_t smem_u32(const void* p) {
    uint32_t a;
    asm("{ .reg .u64 t; cvta.to.shared.u64 t, %1; cvt.u32.u64 %0, t; }" : "=r"(a) : "l"(p));
    return a;
}
__device__ __forceinline__ void cp16(uint32_t dst, const void* src, int srcbytes) {
    asm volatile("cp.async.cg.shared.global [%0], [%1], 16, %2;"
                 :: "r"(dst), "l"(src), "r"(srcbytes) : "memory");
}
__device__ __forceinline__ void cp_commit() {
    asm volatile("cp.async.commit_group;" ::: "memory");
}
template <int N>
__device__ __forceinline__ void cp_wait() {
    asm volatile("cp.async.wait_group %0;" :: "n"(N) : "memory");
}
__device__ __forceinline__ void ldsm_x4(uint32_t* r, uint32_t addr) {
    asm volatile("ldmatrix.sync.aligned.m8n8.x4.shared.b16 {%0,%1,%2,%3}, [%4];"
                 : "=r"(r[0]), "=r"(r[1]), "=r"(r[2]), "=r"(r[3]) : "r"(addr));
}
__device__ __forceinline__ void ldsm_x2(uint32_t* r, uint32_t addr) {
    asm volatile("ldmatrix.sync.aligned.m8n8.x2.shared.b16 {%0,%1}, [%2];"
                 : "=r"(r[0]), "=r"(r[1]) : "r"(addr));
}
__device__ __forceinline__ void mma_bf16(float* c, const uint32_t* a, const uint32_t* b) {
    asm volatile(
        "mma.sync.aligned.m16n8k16.row.col.f32.bf16.bf16.f32 "
        "{%0,%1,%2,%3},{%4,%5,%6,%7},{%8,%9},{%0,%1,%2,%3};"
        : "+f"(c[0]), "+f"(c[1]), "+f"(c[2]), "+f"(c[3])
        : "r"(a[0]), "r"(a[1]), "r"(a[2]), "r"(a[3]), "r"(b[0]), "r"(b[1]));
}

// ---------------- routing + converts -----------------------------------------
__global__ void k_zero() {
    int i = threadIdx.x;
    if (i < NE) { g_cnt[i] = 0; g_cur[i] = 0; }
}
// merged: histogram count + fp32->bf16 convert of x (independent work)
__global__ void k_count_cvt(const int* __restrict__ ids, const float* __restrict__ x) {
    int i = blockIdx.x * blockDim.x + threadIdx.x;      // over NTOK*DIM/4 float4s
    float4 v = ((const float4*)x)[i];
    union { __nv_bfloat162 h; uint32_t u; } a, b;
    a.h = __floats2bfloat162_rn(v.x, v.y);
    b.h = __floats2bfloat162_rn(v.z, v.w);
    ((uint2*)g_Xb)[i] = make_uint2(a.u, b.u);
    if (i < NTOK) atomicAdd(&g_cnt[ids[i]], 1);
}
__global__ void k_scan() {
    if (threadIdx.x == 0) {
        int s = 0;
        for (int e = 0; e < NE; e++) { g_off[e] = s; s += g_cnt[e]; }
        int t = 0;
        for (int e = 0; e < NE; e++) {
            int nt = (g_cnt[e] + 127) >> 7;
            for (int q = 0; q < nt; q++) g_tileTab[t++] = (e << 16) | q;
        }
        g_ntile = t;
    }
}
__global__ void k_scatter(const int* __restrict__ ids) {
    int i = blockIdx.x * blockDim.x + threadIdx.x;
    if (i < NTOK) {
        int e = ids[i];
        int p = g_off[e] + atomicAdd(&g_cur[e], 1);
        g_perm[p] = i;
    }
}
__global__ void k_gather(const float* __restrict__ x) {
    int p   = blockIdx.x;
    int src = g_perm[p];
    float4 v = ((const float4*)(x + (size_t)src * DIM))[threadIdx.x];
    ((float4*)(g_Xg + (size_t)p * DIM))[threadIdx.x] = v;
    union { __nv_bfloat162 h; uint32_t u; } a, b;
    a.h = __floats2bfloat162_rn(v.x, v.y);
    b.h = __floats2bfloat162_rn(v.z, v.w);
    ((uint2*)(g_Xgb + (size_t)p * DIM))[threadIdx.x] = make_uint2(a.u, b.u);
}

// ---------------- single merged transpose+convert launch ---------------------
// Block counts per weight: s1 (FFN/32)*(DIM/32)=4096, s2 4096, sg 1024,
// d1 40960, d2 40960, dg 10240. Total 101376.
__global__ void k_transpose_all(
    const float* __restrict__ sW1, const float* __restrict__ sW2,
    const float* __restrict__ sWg, const float* __restrict__ dW1,
    const float* __restrict__ dW2, const float* __restrict__ dWg)
{
    int b = blockIdx.x;
    const float* W; bf16* Wt; int K, N;
    if (b < 4096)                { W = sW1; Wt = g_sW1t; K = DIM; N = FFN; }
    else if ((b -= 4096) < 4096) { W = sW2; Wt = g_sW2t; K = FFN; N = DIM; }
    else if ((b -= 4096) < 1024) { W = sWg; Wt = g_sWgt; K = DIM; N = DIM; }
    else if ((b -= 1024) < 40960) {
        int e = b / 4096; b -= e * 4096;
        W = dW1 + (size_t)e * DIM * FFN; Wt = g_dW1t + (size_t)e * DIM * FFN;
        K = DIM; N = FFN;
    }
    else if ((b -= 40960) < 40960) {
        int e = b / 4096; b -= e * 4096;
        W = dW2 + (size_t)e * DIM * FFN; Wt = g_dW2t + (size_t)e * DIM * FFN;
        K = FFN; N = DIM;
    }
    else {
        b -= 40960;
        int e = b / 1024; b -= e * 1024;
        W = dWg + (size_t)e * DIM * DIM; Wt = g_dWgt + (size_t)e * DIM * DIM;
        K = DIM; N = DIM;
    }
    int nb = N >> 5;
    int n0 = (b % nb) * 32, k0 = (b / nb) * 32;

    __shared__ float t[32][33];
#pragma unroll
    for (int i = threadIdx.y; i < 32; i += 8)
        t[i][threadIdx.x] = W[(size_t)(k0 + i) * N + n0 + threadIdx.x];
    __syncthreads();
#pragma unroll
    for (int i = threadIdx.y; i < 32; i += 8)
        Wt[(size_t)(n0 + i) * K + k0 + threadIdx.x] = __float2bfloat16(t[threadIdx.x][i]);
}

// ---------------- tiling -----------------------------------------------------
// BM=128, BN=128, BK=64, 256 threads (8 warps 2x4), warp tile 64x32.
// 3-stage cp.async pipeline, one __syncthreads per K-chunk. (R7 proven config.)
#define ROWB   144
#define BUFBY  (128 * ROWB)
#define STAGES 3
#define SMEM_BYTES (STAGES * 2 * BUFBY)    // 110592

__device__ __forceinline__ bool tile_coords(int by, int domSel, bool& dom, int& e,
                                            int& Mloc, int& rowBase, int& rowTile) {
    if (domSel < 0) { dom = by >= 64; if (dom) by -= 64; }
    else            dom = domSel != 0;
    if (!dom) {
        e = 0; Mloc = NTOK; rowBase = 0; rowTile = by * 128;
    } else {
        if (by >= g_ntile) return false;
        int pk  = g_tileTab[by];
        e       = pk >> 16;
        rowTile = (pk & 0xffff) * 128;
        Mloc    = g_cnt[e];
        rowBase = g_off[e];
    }
    return true;
}

// MODE 0: acts = bf16(gelu(x@W1+b1));  MODE 1: h = A@W2+b2+x;  MODE 2: gate+mix
template <int MODE>
__global__ void __launch_bounds__(256, 2) gemm_bf(
    const float* __restrict__ xf,
    const float* __restrict__ sbias, const float* __restrict__ dbias,
    float* __restrict__ Fout, int K, int Nd, int domSel)
{
    bool dom; int e, Mloc, rowBase, rowTile;
    if (!tile_coords(blockIdx.y, domSel, dom, e, Mloc, rowBase, rowTile)) return;

    const bf16* A;
    if (MODE == 1) A = (dom ? g_Ad : g_Ab) + (dom ? (size_t)rowBase * K : 0);
    else           A = dom ? g_Xgb + (size_t)rowBase * K : g_Xb;
    const bf16* Wt =
        MODE == 0 ? (dom ? g_dW1t + (size_t)e * K * Nd : g_sW1t)
      : MODE == 1 ? (dom ? g_dW2t + (size_t)e * K * Nd : g_sW2t)
                  : (dom ? g_dWgt + (size_t)e * K * Nd : g_sWgt);
    const float* bias = dom ? dbias + (size_t)e * Nd : sbias;
    const float* Xr   = dom ? g_Xg : xf;

    extern __shared__ uint8_t sm[];
    uint32_t asb = smem_u32(sm);
    uint32_t bsb = asb + STAGES * BUFBY;

    int tid   = threadIdx.x;
    int lane  = tid & 31;
    int warp  = tid >> 5;
    int warpM = warp >> 2;
    int warpN = warp & 3;
    int colTile = blockIdx.x * 128;

    int srow = tid >> 3;             // 0..31 (+p*32)
    int sseg = (tid & 7) * 8;        // bf16 elems, 0..56

    int aoffB = (lane & 15) * ROWB + ((lane >> 4) << 4);
    int boffB = (lane & 7)  * ROWB + (((lane >> 3) & 1) << 4);

    float acc[4][4][4];
#pragma unroll
    for (int mi = 0; mi < 4; mi++)
#pragma unroll
        for (int ni = 0; ni < 4; ni++)
#pragma unroll
            for (int j = 0; j < 4; j++) acc[mi][ni][j] = 0.f;

    const int chunks = K >> 6;

#define ISSUE(chunk, slot)                                                        \
    do {                                                                          \
        int _kk = (chunk) << 6;                                                   \
        uint32_t _aO = asb + (uint32_t)(slot) * BUFBY;                            \
        uint32_t _bO = bsb + (uint32_t)(slot) * BUFBY;                            \
        _Pragma("unroll")                                                         \
        for (int _p = 0; _p < 4; _p++) {                                          \
            int _row = srow + _p * 32;                                            \
            int _av  = (rowTile + _row) < Mloc ? 16 : 0;                          \
            cp16(_aO + (uint32_t)(_row * ROWB + sseg * 2),                        \
                 A + (size_t)(rowTile + _row) * K + _kk + sseg, _av);             \
            cp16(_bO + (uint32_t)(_row * ROWB + sseg * 2),                        \
                 Wt + (size_t)(colTile + _row) * K + _kk + sseg, 16);             \
        }                                                                         \
        cp_commit();                                                              \
    } while (0)

    ISSUE(0, 0);
    ISSUE(1, 1);

    int sCur = 0;
    for (int i = 0; i < chunks; i++) {
        if (i + 1 < chunks) cp_wait<1>();
        else                cp_wait<0>();
        __syncthreads();
        if (i + 2 < chunks) {
            int slot = sCur + 2; if (slot >= STAGES) slot -= STAGES;
            ISSUE(i + 2, slot);
        }
        uint32_t aBuf = asb + (uint32_t)sCur * BUFBY;
        uint32_t bBuf = bsb + (uint32_t)sCur * BUFBY;
#pragma unroll
        for (int kb = 0; kb < 64; kb += 16) {
            uint32_t af[4][4], bfr[4][2];
#pragma unroll
            for (int mi = 0; mi < 4; mi++)
                ldsm_x4(af[mi], aBuf + (uint32_t)((warpM * 64 + mi * 16) * ROWB + kb * 2 + aoffB));
#pragma unroll
            for (int ni = 0; ni < 4; ni++)
                ldsm_x2(bfr[ni], bBuf + (uint32_t)((warpN * 32 + ni * 8) * ROWB + kb * 2 + boffB));
#pragma unroll
            for (int mi = 0; mi < 4; mi++)
#pragma unroll
                for (int ni = 0; ni < 4; ni++)
                    mma_bf16(acc[mi][ni], af[mi], bfr[ni]);
        }
        if (++sCur == STAGES) sCur = 0;
    }
#undef ISSUE

    // ---------------- epilogue ----------------
    int grp = lane >> 2, t4 = lane & 3;
#pragma unroll
    for (int mi = 0; mi < 4; mi++)
#pragma unroll
        for (int h = 0; h < 2; h++) {
            int lr = rowTile + warpM * 64 + mi * 16 + grp + h * 8;
            if (lr >= Mloc) continue;
            int grow = dom ? rowBase + lr : lr;
#pragma unroll
            for (int ni = 0; ni < 4; ni++) {
                int col = colTile + warpN * 32 + ni * 8 + t4 * 2;
                float v0 = acc[mi][ni][h * 2 + 0];
                float v1 = acc[mi][ni][h * 2 + 1];
                if (MODE == 0) {
                    float a0 = v0 + bias[col];
                    float a1 = v1 + bias[col + 1];
                    a0 = 0.5f * a0 * (1.0f + erff(a0 * 0.70710678118654752f));
                    a1 = 0.5f * a1 * (1.0f + erff(a1 * 0.70710678118654752f));
                    union { __nv_bfloat162 h2; uint32_t u; } cv;
                    cv.h2 = __floats2bfloat162_rn(a0, a1);
                    *(uint32_t*)((dom ? g_Ad : g_Ab) + (size_t)grow * Nd + col) = cv.u;
                } else if (MODE == 1) {
                    float*       dst = (dom ? g_Hd : g_H) + (size_t)grow * Nd + col;
                    const float* r   = Xr + (size_t)grow * Nd + col;
                    dst[0] = v0 + bias[col]     + r[0];
                    dst[1] = v1 + bias[col + 1] + r[1];
                } else {
                    const float* hp = (dom ? g_Hd : g_H) + (size_t)grow * Nd + col;
                    const float* xp = Xr + (size_t)grow * Nd + col;
                    int orow = dom ? g_perm[grow] : grow;
                    float* dst = Fout + (size_t)orow * Nd + col;
                    float g0 = 1.0f / (1.0f + expf(-(v0 + bias[col])));
                    float g1 = 1.0f / (1.0f + expf(-(v1 + bias[col + 1])));
                    float o0 = g0 * hp[0] + (1.0f - g0) * xp[0];
                    float o1 = g1 * hp[1] + (1.0f - g1) * xp[1];
                    if (dom) { dst[0] += o0; dst[1] += o1; }
                    else     { dst[0]  = o0; dst[1]  = o1; }
                }
            }
        }
}

// ---------------- launch -----------------------------------------------------
extern "C" void kernel_launch(void* const* d_in, const int* in_sizes, int n_in,
                              void* d_out, int out_size)
{
    const float* x   = (const float*)d_in[0];
    const int*   ids = (const int*)  d_in[1];
    const float* sW1 = (const float*)d_in[2];
    const float* sb1 = (const float*)d_in[3];
    const float* sW2 = (const float*)d_in[4];
    const float* sb2 = (const float*)d_in[5];
    const float* sWg = (const float*)d_in[6];
    const float* sbg = (const float*)d_in[7];
    const float* dW1 = (const float*)d_in[8];
    const float* db1 = (const float*)d_in[9];
    const float* dW2 = (const float*)d_in[10];
    const float* db2 = (const float*)d_in[11];
    const float* dWg = (const float*)d_in[12];
    const float* dbg = (const float*)d_in[13];
    float* out = (float*)d_out;

    cudaFuncSetAttribute(gemm_bf<0>, cudaFuncAttributeMaxDynamicSharedMemorySize, SMEM_BYTES);
    cudaFuncSetAttribute(gemm_bf<1>, cudaFuncAttributeMaxDynamicSharedMemorySize, SMEM_BYTES);
    cudaFuncSetAttribute(gemm_bf<2>, cudaFuncAttributeMaxDynamicSharedMemorySize, SMEM_BYTES);

    // routing + converts (count fused with x-convert)
    k_zero     <<<1, 32>>>();
    k_count_cvt<<<NTOK * DIM / 4 / 256, 256>>>(ids, x);
    k_scan     <<<1, 32>>>();
    k_scatter  <<<NTOK / 256, 256>>>(ids);
    k_gather   <<<NTOK, 256>>>(x);

    // all weight transposes+converts in ONE launch
    k_transpose_all<<<101376, dim3(32, 8)>>>(sW1, sW2, sWg, dW1, dW2, dWg);

    // GEMM1 merged (shared gridY 0..63, domain 64..137)
    gemm_bf<0><<<dim3(FFN / 128, 138), 256, SMEM_BYTES>>>(x, sb1, db1, nullptr, DIM, FFN, -1);
    // GEMM2 merged
    gemm_bf<1><<<dim3(DIM / 128, 138), 256, SMEM_BYTES>>>(x, sb2, db2, nullptr, FFN, DIM, -1);
    // GEMM3 gate+mix: shared store first, then domain accumulate (ordering!)
    gemm_bf<2><<<dim3(DIM / 128, 64), 256, SMEM_BYTES>>>(x, sbg, dbg, out, DIM, DIM, 0);
    gemm_bf<2><<<dim3(DIM / 128, 74), 256, SMEM_BYTES>>>(x, sbg, dbg, out, DIM, DIM, 1);
}

// round 11
// speedup vs baseline: 1.3439x; 1.0612x over previous
#include <cuda_runtime.h>
#include <cuda_bf16.h>
#include <math.h>
#include <stdint.h>

#define NTOK 8192
#define DIM  1024
#define FFN  4096
#define NE   10

typedef __nv_bfloat16 bf16;

// ---------------- scratch (device globals: no allocation allowed) ----------
__device__ bf16  g_Ab [(size_t)NTOK * FFN];   // shared gelu acts (token rows)
__device__ bf16  g_Ad [(size_t)NTOK * FFN];   // domain gelu acts (perm rows)
__device__ float g_G  [(size_t)NTOK * DIM];   // shared gate values (token rows)
__device__ float g_Gd [(size_t)NTOK * DIM];   // domain gate values (perm rows)
__device__ float g_Od [(size_t)NTOK * DIM];   // domain mix output (perm rows)
__device__ float g_Xg [(size_t)NTOK * DIM];   // gathered x fp32 (perm rows)
__device__ bf16  g_Xb [(size_t)NTOK * DIM];   // x bf16 (token rows)
__device__ bf16  g_Xgb[(size_t)NTOK * DIM];   // gathered x bf16 (perm rows)
__device__ int   g_perm[NTOK];
__device__ int   g_cnt[NE];
__device__ int   g_off[NE];
__device__ int   g_cur[NE];
__device__ int   g_tileTab[80];
__device__ int   g_ntile;

// transposed bf16 weights: Wt[n*K + k] = bf16(W[k*N + n])
__device__ bf16 g_sW1t[(size_t)FFN * DIM];
__device__ bf16 g_sW2t[(size_t)DIM * FFN];
__device__ bf16 g_sWgt[(size_t)DIM * DIM];
__device__ bf16 g_dW1t[(size_t)NE * FFN * DIM];
__device__ bf16 g_dW2t[(size_t)NE * DIM * FFN];
__device__ bf16 g_dWgt[(size_t)NE * DIM * DIM];

// ---------------- PTX helpers ------------------------------------------------
__device__ __forceinline__ uint32_t smem_u32(const void* p) {
    uint32_t a;
    asm("{ .reg .u64 t; cvta.to.shared.u64 t, %1; cvt.u32.u64 %0, t; }" : "=r"(a) : "l"(p));
    return a;
}
__device__ __forceinline__ void cp16(uint32_t dst, const void* src, int srcbytes) {
    asm volatile("cp.async.cg.shared.global [%0], [%1], 16, %2;"
                 :: "r"(dst), "l"(src), "r"(srcbytes) : "memory");
}
__device__ __forceinline__ void cp_commit() {
    asm volatile("cp.async.commit_group;" ::: "memory");
}
template <int N>
__device__ __forceinline__ void cp_wait() {
    asm volatile("cp.async.wait_group %0;" :: "n"(N) : "memory");
}
__device__ __forceinline__ void ldsm_x4(uint32_t* r, uint32_t addr) {
    asm volatile("ldmatrix.sync.aligned.m8n8.x4.shared.b16 {%0,%1,%2,%3}, [%4];"
                 : "=r"(r[0]), "=r"(r[1]), "=r"(r[2]), "=r"(r[3]) : "r"(addr));
}
__device__ __forceinline__ void ldsm_x2(uint32_t* r, uint32_t addr) {
    asm volatile("ldmatrix.sync.aligned.m8n8.x2.shared.b16 {%0,%1}, [%2];"
                 : "=r"(r[0]), "=r"(r[1]) : "r"(addr));
}
__device__ __forceinline__ void mma_bf16(float* c, const uint32_t* a, const uint32_t* b) {
    asm volatile(
        "mma.sync.aligned.m16n8k16.row.col.f32.bf16.bf16.f32 "
        "{%0,%1,%2,%3},{%4,%5,%6,%7},{%8,%9},{%0,%1,%2,%3};"
        : "+f"(c[0]), "+f"(c[1]), "+f"(c[2]), "+f"(c[3])
        : "r"(a[0]), "r"(a[1]), "r"(a[2]), "r"(a[3]), "r"(b[0]), "r"(b[1]));
}

// ---------------- routing + converts -----------------------------------------
__global__ void k_zero() {
    int i = threadIdx.x;
    if (i < NE) { g_cnt[i] = 0; g_cur[i] = 0; }
}
__global__ void k_count_cvt(const int* __restrict__ ids, const float* __restrict__ x) {
    int i = blockIdx.x * blockDim.x + threadIdx.x;
    float4 v = ((const float4*)x)[i];
    union { __nv_bfloat162 h; uint32_t u; } a, b;
    a.h = __floats2bfloat162_rn(v.x, v.y);
    b.h = __floats2bfloat162_rn(v.z, v.w);
    ((uint2*)g_Xb)[i] = make_uint2(a.u, b.u);
    if (i < NTOK) atomicAdd(&g_cnt[ids[i]], 1);
}
__global__ void k_scan() {
    if (threadIdx.x == 0) {
        int s = 0;
        for (int e = 0; e < NE; e++) { g_off[e] = s; s += g_cnt[e]; }
        int t = 0;
        for (int e = 0; e < NE; e++) {
            int nt = (g_cnt[e] + 127) >> 7;
            for (int q = 0; q < nt; q++) g_tileTab[t++] = (e << 16) | q;
        }
        g_ntile = t;
    }
}
__global__ void k_scatter(const int* __restrict__ ids) {
    int i = blockIdx.x * blockDim.x + threadIdx.x;
    if (i < NTOK) {
        int e = ids[i];
        int p = g_off[e] + atomicAdd(&g_cur[e], 1);
        g_perm[p] = i;
    }
}
__global__ void k_gather(const float* __restrict__ x) {
    int p   = blockIdx.x;
    int src = g_perm[p];
    float4 v = ((const float4*)(x + (size_t)src * DIM))[threadIdx.x];
    ((float4*)(g_Xg + (size_t)p * DIM))[threadIdx.x] = v;
    union { __nv_bfloat162 h; uint32_t u; } a, b;
    a.h = __floats2bfloat162_rn(v.x, v.y);
    b.h = __floats2bfloat162_rn(v.z, v.w);
    ((uint2*)(g_Xgb + (size_t)p * DIM))[threadIdx.x] = make_uint2(a.u, b.u);
}
// combine: out[perm[p]] += domain mix row p  (single writer per element)
__global__ void k_combine(float* __restrict__ out) {
    int p = blockIdx.x;
    int t = g_perm[p];
    float4* o = (float4*)(out + (size_t)t * DIM);
    const float4* s = (const float4*)(g_Od + (size_t)p * DIM);
    float4 a = o[threadIdx.x], b = s[threadIdx.x];
    a.x += b.x; a.y += b.y; a.z += b.z; a.w += b.w;
    o[threadIdx.x] = a;
}

// ---------------- single merged transpose+convert launch ---------------------
__global__ void k_transpose_all(
    const float* __restrict__ sW1, const float* __restrict__ sW2,
    const float* __restrict__ sWg, const float* __restrict__ dW1,
    const float* __restrict__ dW2, const float* __restrict__ dWg)
{
    int b = blockIdx.x;
    const float* W; bf16* Wt; int K, N;
    if (b < 4096)                { W = sW1; Wt = g_sW1t; K = DIM; N = FFN; }
    else if ((b -= 4096) < 4096) { W = sW2; Wt = g_sW2t; K = FFN; N = DIM; }
    else if ((b -= 4096) < 1024) { W = sWg; Wt = g_sWgt; K = DIM; N = DIM; }
    else if ((b -= 1024) < 40960) {
        int e = b / 4096; b -= e * 4096;
        W = dW1 + (size_t)e * DIM * FFN; Wt = g_dW1t + (size_t)e * DIM * FFN;
        K = DIM; N = FFN;
    }
    else if ((b -= 40960) < 40960) {
        int e = b / 4096; b -= e * 4096;
        W = dW2 + (size_t)e * DIM * FFN; Wt = g_dW2t + (size_t)e * DIM * FFN;
        K = FFN; N = DIM;
    }
    else {
        b -= 40960;
        int e = b / 1024; b -= e * 1024;
        W = dWg + (size_t)e * DIM * DIM; Wt = g_dWgt + (size_t)e * DIM * DIM;
        K = DIM; N = DIM;
    }
    int nb = N >> 5;
    int n0 = (b % nb) * 32, k0 = (b / nb) * 32;

    __shared__ float t[32][33];
#pragma unroll
    for (int i = threadIdx.y; i < 32; i += 8)
        t[i][threadIdx.x] = W[(size_t)(k0 + i) * N + n0 + threadIdx.x];
    __syncthreads();
#pragma unroll
    for (int i = threadIdx.y; i < 32; i += 8)
        Wt[(size_t)(n0 + i) * K + k0 + threadIdx.x] = __float2bfloat16(t[threadIdx.x][i]);
}

// ---------------- unified GEMM -----------------------------------------------
// BM=128, BN=128, BK=64, 256 threads (8 warps 2x4), warp tile 64x32,
// 3-stage cp.async pipeline (R7/R10 proven config).
// phase 0 (launch A): gy<138 -> GEMM1 acts; gy in [138,202) -> gate shared;
//                     gy in [202,276) -> gate domain. Gate stores fp32 g.
// phase 1 (launch B): GEMM2 + final mix epilogue (h in registers only).
#define ROWB   144
#define BUFBY  (128 * ROWB)
#define STAGES 3
#define SMEM_BYTES (STAGES * 2 * BUFBY)

#define TASK_ACT  0
#define TASK_GATE 1
#define TASK_MIX  2

__device__ __forceinline__ bool dom_tile(int idx, int& e, int& Mloc,
                                         int& rowBase, int& rowTile) {
    if (idx >= g_ntile) return false;
    int pk  = g_tileTab[idx];
    e       = pk >> 16;
    rowTile = (pk & 0xffff) * 128;
    Mloc    = g_cnt[e];
    rowBase = g_off[e];
    return true;
}

__global__ void __launch_bounds__(256, 2) gemm_uni(
    int phase, const float* __restrict__ xf,
    const float* __restrict__ sb1, const float* __restrict__ db1,
    const float* __restrict__ sbg, const float* __restrict__ dbg,
    const float* __restrict__ sb2, const float* __restrict__ db2,
    float* __restrict__ out)
{
    int task, K, Nd;
    bool dom; int e = 0, Mloc = NTOK, rowBase = 0, rowTile;
    const bf16 *A, *Wt;
    const float* bias;

    int gy = blockIdx.y;
    if (phase == 0) {
        if (gy < 138) {
            task = TASK_ACT; K = DIM; Nd = FFN;
            dom = gy >= 64;
            if (!dom) { rowTile = gy * 128; }
            else if (!dom_tile(gy - 64, e, Mloc, rowBase, rowTile)) return;
            A    = dom ? g_Xgb + (size_t)rowBase * K : g_Xb;
            Wt   = dom ? g_dW1t + (size_t)e * K * Nd : g_sW1t;
            bias = dom ? db1 + (size_t)e * Nd : sb1;
        } else if (gy < 202) {
            if (blockIdx.x >= 8) return;
            task = TASK_GATE; K = DIM; Nd = DIM; dom = false;
            rowTile = (gy - 138) * 128;
            A = g_Xb; Wt = g_sWgt; bias = sbg;
        } else {
            if (blockIdx.x >= 8) return;
            task = TASK_GATE; K = DIM; Nd = DIM; dom = true;
            if (!dom_tile(gy - 202, e, Mloc, rowBase, rowTile)) return;
            A    = g_Xgb + (size_t)rowBase * K;
            Wt   = g_dWgt + (size_t)e * K * Nd;
            bias = dbg + (size_t)e * Nd;
        }
    } else {
        task = TASK_MIX; K = FFN; Nd = DIM;
        dom = gy >= 64;
        if (!dom) { rowTile = gy * 128; }
        else if (!dom_tile(gy - 64, e, Mloc, rowBase, rowTile)) return;
        A    = (dom ? g_Ad : g_Ab) + (dom ? (size_t)rowBase * K : 0);
        Wt   = dom ? g_dW2t + (size_t)e * K * Nd : g_sW2t;
        bias = dom ? db2 + (size_t)e * Nd : sb2;
    }

    extern __shared__ uint8_t sm[];
    uint32_t asb = smem_u32(sm);
    uint32_t bsb = asb + STAGES * BUFBY;

    int tid   = threadIdx.x;
    int lane  = tid & 31;
    int warp  = tid >> 5;
    int warpM = warp >> 2;
    int warpN = warp & 3;
    int colTile = blockIdx.x * 128;

    int srow = tid >> 3;
    int sseg = (tid & 7) * 8;

    int aoffB = (lane & 15) * ROWB + ((lane >> 4) << 4);
    int boffB = (lane & 7)  * ROWB + (((lane >> 3) & 1) << 4);

    float acc[4][4][4];
#pragma unroll
    for (int mi = 0; mi < 4; mi++)
#pragma unroll
        for (int ni = 0; ni < 4; ni++)
#pragma unroll
            for (int j = 0; j < 4; j++) acc[mi][ni][j] = 0.f;

    const int chunks = K >> 6;

#define ISSUE(chunk, slot)                                                        \
    do {                                                                          \
        int _kk = (chunk) << 6;                                                   \
        uint32_t _aO = asb + (uint32_t)(slot) * BUFBY;                            \
        uint32_t _bO = bsb + (uint32_t)(slot) * BUFBY;                            \
        _Pragma("unroll")                                                         \
        for (int _p = 0; _p < 4; _p++) {                                          \
            int _row = srow + _p * 32;                                            \
            int _av  = (rowTile + _row) < Mloc ? 16 : 0;                          \
            cp16(_aO + (uint32_t)(_row * ROWB + sseg * 2),                        \
                 A + (size_t)(rowTile + _row) * K + _kk + sseg, _av);             \
            cp16(_bO + (uint32_t)(_row * ROWB + sseg * 2),                        \
                 Wt + (size_t)(colTile + _row) * K + _kk + sseg, 16);             \
        }                                                                         \
        cp_commit();                                                              \
    } while (0)

    ISSUE(0, 0);
    ISSUE(1, 1);

    int sCur = 0;
    for (int i = 0; i < chunks; i++) {
        if (i + 1 < chunks) cp_wait<1>();
        else                cp_wait<0>();
        __syncthreads();
        if (i + 2 < chunks) {
            int slot = sCur + 2; if (slot >= STAGES) slot -= STAGES;
            ISSUE(i + 2, slot);
        }
        uint32_t aBuf = asb + (uint32_t)sCur * BUFBY;
        uint32_t bBuf = bsb + (uint32_t)sCur * BUFBY;
#pragma unroll
        for (int kb = 0; kb < 64; kb += 16) {
            uint32_t af[4][4], bfr[4][2];
#pragma unroll
            for (int mi = 0; mi < 4; mi++)
                ldsm_x4(af[mi], aBuf + (uint32_t)((warpM * 64 + mi * 16) * ROWB + kb * 2 + aoffB));
#pragma unroll
            for (int ni = 0; ni < 4; ni++)
                ldsm_x2(bfr[ni], bBuf + (uint32_t)((warpN * 32 + ni * 8) * ROWB + kb * 2 + boffB));
#pragma unroll
            for (int mi = 0; mi < 4; mi++)
#pragma unroll
                for (int ni = 0; ni < 4; ni++)
                    mma_bf16(acc[mi][ni], af[mi], bfr[ni]);
        }
        if (++sCur == STAGES) sCur = 0;
    }
#undef ISSUE

    // ---------------- epilogue ----------------
    int grp = lane >> 2, t4 = lane & 3;
#pragma unroll
    for (int mi = 0; mi < 4; mi++)
#pragma unroll
        for (int h = 0; h < 2; h++) {
            int lr = rowTile + warpM * 64 + mi * 16 + grp + h * 8;
            if (lr >= Mloc) continue;
            int grow = dom ? rowBase + lr : lr;
#pragma unroll
            for (int ni = 0; ni < 4; ni++) {
                int col = colTile + warpN * 32 + ni * 8 + t4 * 2;
                float v0 = acc[mi][ni][h * 2 + 0];
                float v1 = acc[mi][ni][h * 2 + 1];
                if (task == TASK_ACT) {
                    float a0 = v0 + bias[col];
                    float a1 = v1 + bias[col + 1];
                    a0 = 0.5f * a0 * (1.0f + erff(a0 * 0.70710678118654752f));
                    a1 = 0.5f * a1 * (1.0f + erff(a1 * 0.70710678118654752f));
                    union { __nv_bfloat162 h2; uint32_t u; } cv;
                    cv.h2 = __floats2bfloat162_rn(a0, a1);
                    *(uint32_t*)((dom ? g_Ad : g_Ab) + (size_t)grow * Nd + col) = cv.u;
                } else if (task == TASK_GATE) {
                    float* dst = (dom ? g_Gd : g_G) + (size_t)grow * Nd + col;
                    dst[0] = 1.0f / (1.0f + expf(-(v0 + bias[col])));
                    dst[1] = 1.0f / (1.0f + expf(-(v1 + bias[col + 1])));
                } else {  // TASK_MIX: h in registers; final mix
                    const float* xp = (dom ? g_Xg : xf) + (size_t)grow * Nd + col;
                    const float* gp = (dom ? g_Gd : g_G) + (size_t)grow * Nd + col;
                    float x0 = xp[0], x1 = xp[1];
                    float h0 = v0 + bias[col]     + x0;
                    float h1 = v1 + bias[col + 1] + x1;
                    float g0 = gp[0], g1 = gp[1];
                    float o0 = g0 * h0 + (1.0f - g0) * x0;
                    float o1 = g1 * h1 + (1.0f - g1) * x1;
                    float* dst = (dom ? g_Od + (size_t)grow * Nd
                                      : out + (size_t)grow * Nd) + col;
                    dst[0] = o0;
                    dst[1] = o1;
                }
            }
        }
}

// ---------------- launch -----------------------------------------------------
extern "C" void kernel_launch(void* const* d_in, const int* in_sizes, int n_in,
                              void* d_out, int out_size)
{
    const float* x   = (const float*)d_in[0];
    const int*   ids = (const int*)  d_in[1];
    const float* sW1 = (const float*)d_in[2];
    const float* sb1 = (const float*)d_in[3];
    const float* sW2 = (const float*)d_in[4];
    const float* sb2 = (const float*)d_in[5];
    const float* sWg = (const float*)d_in[6];
    const float* sbg = (const float*)d_in[7];
    const float* dW1 = (const float*)d_in[8];
    const float* db1 = (const float*)d_in[9];
    const float* dW2 = (const float*)d_in[10];
    const float* db2 = (const float*)d_in[11];
    const float* dWg = (const float*)d_in[12];
    const float* dbg = (const float*)d_in[13];
    float* out = (float*)d_out;

    cudaFuncSetAttribute(gemm_uni, cudaFuncAttributeMaxDynamicSharedMemorySize, SMEM_BYTES);

    // routing + converts
    k_zero     <<<1, 32>>>();
    k_count_cvt<<<NTOK * DIM / 4 / 256, 256>>>(ids, x);
    k_scan     <<<1, 32>>>();
    k_scatter  <<<NTOK / 256, 256>>>(ids);
    k_gather   <<<NTOK, 256>>>(x);

    // all weight transposes+converts in one launch
    k_transpose_all<<<101376, dim3(32, 8)>>>(sW1, sW2, sWg, dW1, dW2, dWg);

    // Launch A: GEMM1 (acts, shared+domain) + gate GEMMs (gate values)
    gemm_uni<<<dim3(32, 276), 256, SMEM_BYTES>>>(
        0, x, sb1, db1, sbg, dbg, sb2, db2, out);
    // Launch B: GEMM2 + final mix (h register-only; shared->out, domain->g_Od)
    gemm_uni<<<dim3(8, 138), 256, SMEM_BYTES>>>(
        1, x, sb1, db1, sbg, dbg, sb2, db2, out);
    // Combine: out[perm[p]] += domain mix
    k_combine<<<NTOK, 256>>>(out);
}

// round 12
// speedup vs baseline: 1.3580x; 1.0105x over previous
#include <cuda_runtime.h>
#include <cuda_bf16.h>
#include <math.h>
#include <stdint.h>

#define NTOK 8192
#define DIM  1024
#define FFN  4096
#define NE   10

typedef __nv_bfloat16 bf16;

// ---------------- scratch (device globals: no allocation allowed) ----------
__device__ bf16  g_Ab [(size_t)NTOK * FFN];   // shared gelu acts (token rows)
__device__ bf16  g_Ad [(size_t)NTOK * FFN];   // domain gelu acts (perm rows)
__device__ float g_G  [(size_t)NTOK * DIM];   // shared gate values (token rows)
__device__ float g_Gd [(size_t)NTOK * DIM];   // domain gate values (perm rows)
__device__ float g_Od [(size_t)NTOK * DIM];   // domain mix output (perm rows)
__device__ float g_Xg [(size_t)NTOK * DIM];   // gathered x fp32 (perm rows)
__device__ bf16  g_Xb [(size_t)NTOK * DIM];   // x bf16 (token rows)
__device__ bf16  g_Xgb[(size_t)NTOK * DIM];   // gathered x bf16 (perm rows)
__device__ int   g_perm[NTOK];
__device__ int   g_cnt[NE];
__device__ int   g_off[NE];
__device__ int   g_cur[NE];
__device__ int   g_tileTab[80];
__device__ int   g_ntile;
__device__ int   g_task;                      // persistent task counter
__device__ int   g_rowCnt[160];               // per-row-group producer counters (138 used)

// transposed bf16 weights: Wt[n*K + k] = bf16(W[k*N + n])
__device__ bf16 g_sW1t[(size_t)FFN * DIM];
__device__ bf16 g_sW2t[(size_t)DIM * FFN];
__device__ bf16 g_sWgt[(size_t)DIM * DIM];
__device__ bf16 g_dW1t[(size_t)NE * FFN * DIM];
__device__ bf16 g_dW2t[(size_t)NE * DIM * FFN];
__device__ bf16 g_dWgt[(size_t)NE * DIM * DIM];

// task layout: rows 0..137 (64 shared + 74 domain slots)
//   t in [0, 5520): r = t/40, c = t%40; c<32 -> ACT tile (r, c); else GATE (r, c-32)
//   t in [5520, 6624): MIX tile ((t-5520)>>3, (t-5520)&7)
#define NROW       138
#define TASK_PROD  (NROW * 40)      // 5520
#define TASK_TOTAL (TASK_PROD + NROW * 8)
#define DEP_TARGET 40

// ---------------- PTX helpers ------------------------------------------------
__device__ __forceinline__ uint32_t smem_u32(const void* p) {
    uint32_t a;
    asm("{ .reg .u64 t; cvta.to.shared.u64 t, %1; cvt.u32.u64 %0, t; }" : "=r"(a) : "l"(p));
    return a;
}
__device__ __forceinline__ void cp16(uint32_t dst, const void* src, int srcbytes) {
    asm volatile("cp.async.cg.shared.global [%0], [%1], 16, %2;"
                 :: "r"(dst), "l"(src), "r"(srcbytes) : "memory");
}
__device__ __forceinline__ void cp_commit() {
    asm volatile("cp.async.commit_group;" ::: "memory");
}
template <int N>
__device__ __forceinline__ void cp_wait() {
    asm volatile("cp.async.wait_group %0;" :: "n"(N) : "memory");
}
__device__ __forceinline__ void ldsm_x4(uint32_t* r, uint32_t addr) {
    asm volatile("ldmatrix.sync.aligned.m8n8.x4.shared.b16 {%0,%1,%2,%3}, [%4];"
                 : "=r"(r[0]), "=r"(r[1]), "=r"(r[2]), "=r"(r[3]) : "r"(addr));
}
__device__ __forceinline__ void ldsm_x2(uint32_t* r, uint32_t addr) {
    asm volatile("ldmatrix.sync.aligned.m8n8.x2.shared.b16 {%0,%1}, [%2];"
                 : "=r"(r[0]), "=r"(r[1]) : "r"(addr));
}
__device__ __forceinline__ void mma_bf16(float* c, const uint32_t* a, const uint32_t* b) {
    asm volatile(
        "mma.sync.aligned.m16n8k16.row.col.f32.bf16.bf16.f32 "
        "{%0,%1,%2,%3},{%4,%5,%6,%7},{%8,%9},{%0,%1,%2,%3};"
        : "+f"(c[0]), "+f"(c[1]), "+f"(c[2]), "+f"(c[3])
        : "r"(a[0]), "r"(a[1]), "r"(a[2]), "r"(a[3]), "r"(b[0]), "r"(b[1]));
}

// ---------------- routing + converts -----------------------------------------
__global__ void k_zero() {
    int i = threadIdx.x;
    if (i < NE)  { g_cnt[i] = 0; g_cur[i] = 0; }
    if (i < 160) g_rowCnt[i] = 0;
    if (i == 255) g_task = 0;
}
__global__ void k_count_cvt(const int* __restrict__ ids, const float* __restrict__ x) {
    int i = blockIdx.x * blockDim.x + threadIdx.x;
    float4 v = ((const float4*)x)[i];
    union { __nv_bfloat162 h; uint32_t u; } a, b;
    a.h = __floats2bfloat162_rn(v.x, v.y);
    b.h = __floats2bfloat162_rn(v.z, v.w);
    ((uint2*)g_Xb)[i] = make_uint2(a.u, b.u);
    if (i < NTOK) atomicAdd(&g_cnt[ids[i]], 1);
}
__global__ void k_scan() {
    if (threadIdx.x == 0) {
        int s = 0;
        for (int e = 0; e < NE; e++) { g_off[e] = s; s += g_cnt[e]; }
        int t = 0;
        for (int e = 0; e < NE; e++) {
            int nt = (g_cnt[e] + 127) >> 7;
            for (int q = 0; q < nt; q++) g_tileTab[t++] = (e << 16) | q;
        }
        g_ntile = t;
    }
}
__global__ void k_scatter(const int* __restrict__ ids) {
    int i = blockIdx.x * blockDim.x + threadIdx.x;
    if (i < NTOK) {
        int e = ids[i];
        int p = g_off[e] + atomicAdd(&g_cur[e], 1);
        g_perm[p] = i;
    }
}
__global__ void k_gather(const float* __restrict__ x) {
    int p   = blockIdx.x;
    int src = g_perm[p];
    float4 v = ((const float4*)(x + (size_t)src * DIM))[threadIdx.x];
    ((float4*)(g_Xg + (size_t)p * DIM))[threadIdx.x] = v;
    union { __nv_bfloat162 h; uint32_t u; } a, b;
    a.h = __floats2bfloat162_rn(v.x, v.y);
    b.h = __floats2bfloat162_rn(v.z, v.w);
    ((uint2*)(g_Xgb + (size_t)p * DIM))[threadIdx.x] = make_uint2(a.u, b.u);
}
__global__ void k_combine(float* __restrict__ out) {
    int p = blockIdx.x;
    int t = g_perm[p];
    float4* o = (float4*)(out + (size_t)t * DIM);
    const float4* s = (const float4*)(g_Od + (size_t)p * DIM);
    float4 a = o[threadIdx.x], b = s[threadIdx.x];
    a.x += b.x; a.y += b.y; a.z += b.z; a.w += b.w;
    o[threadIdx.x] = a;
}

// ---------------- single merged transpose+convert launch ---------------------
__global__ void k_transpose_all(
    const float* __restrict__ sW1, const float* __restrict__ sW2,
    const float* __restrict__ sWg, const float* __restrict__ dW1,
    const float* __restrict__ dW2, const float* __restrict__ dWg)
{
    int b = blockIdx.x;
    const float* W; bf16* Wt; int K, N;
    if (b < 4096)                { W = sW1; Wt = g_sW1t; K = DIM; N = FFN; }
    else if ((b -= 4096) < 4096) { W = sW2; Wt = g_sW2t; K = FFN; N = DIM; }
    else if ((b -= 4096) < 1024) { W = sWg; Wt = g_sWgt; K = DIM; N = DIM; }
    else if ((b -= 1024) < 40960) {
        int e = b / 4096; b -= e * 4096;
        W = dW1 + (size_t)e * DIM * FFN; Wt = g_dW1t + (size_t)e * DIM * FFN;
        K = DIM; N = FFN;
    }
    else if ((b -= 40960) < 40960) {
        int e = b / 4096; b -= e * 4096;
        W = dW2 + (size_t)e * DIM * FFN; Wt = g_dW2t + (size_t)e * DIM * FFN;
        K = FFN; N = DIM;
    }
    else {
        b -= 40960;
        int e = b / 1024; b -= e * 1024;
        W = dWg + (size_t)e * DIM * DIM; Wt = g_dWgt + (size_t)e * DIM * DIM;
        K = DIM; N = DIM;
    }
    int nb = N >> 5;
    int n0 = (b % nb) * 32, k0 = (b / nb) * 32;

    __shared__ float t[32][33];
#pragma unroll
    for (int i = threadIdx.y; i < 32; i += 8)
        t[i][threadIdx.x] = W[(size_t)(k0 + i) * N + n0 + threadIdx.x];
    __syncthreads();
#pragma unroll
    for (int i = threadIdx.y; i < 32; i += 8)
        Wt[(size_t)(n0 + i) * K + k0 + threadIdx.x] = __float2bfloat16(t[threadIdx.x][i]);
}

// ---------------- persistent fused GEMM --------------------------------------
// BM=128, BN=128, BK=64, 256 threads (8 warps 2x4), 3-stage cp.async pipeline.
#define ROWB   144
#define BUFBY  (128 * ROWB)
#define STAGES 3
#define SMEM_BYTES (STAGES * 2 * BUFBY)

#define TASK_ACT  0
#define TASK_GATE 1
#define TASK_MIX  2

__device__ __forceinline__ bool dom_tile(int idx, int& e, int& Mloc,
                                         int& rowBase, int& rowTile) {
    if (idx >= g_ntile) return false;
    int pk  = g_tileTab[idx];
    e       = pk >> 16;
    rowTile = (pk & 0xffff) * 128;
    Mloc    = g_cnt[e];
    rowBase = g_off[e];
    return true;
}

__global__ void __launch_bounds__(256, 2) gemm_persist(
    const float* __restrict__ xf,
    const float* __restrict__ sb1, const float* __restrict__ db1,
    const float* __restrict__ sbg, const float* __restrict__ dbg,
    const float* __restrict__ sb2, const float* __restrict__ db2,
    float* __restrict__ out)
{
    extern __shared__ uint8_t sm[];
    __shared__ int s_task;
    uint32_t asb = smem_u32(sm);
    uint32_t bsb = asb + STAGES * BUFBY;

    int tid   = threadIdx.x;
    int lane  = tid & 31;
    int warp  = tid >> 5;
    int warpM = warp >> 2;
    int warpN = warp & 3;

    int srow = tid >> 3;
    int sseg = (tid & 7) * 8;
    int aoffB = (lane & 15) * ROWB + ((lane >> 4) << 4);
    int boffB = (lane & 7)  * ROWB + (((lane >> 3) & 1) << 4);
    int grp = lane >> 2, t4 = lane & 3;

    for (;;) {
        if (tid == 0) s_task = atomicAdd(&g_task, 1);
        __syncthreads();                  // also: all warps done with prior tile's smem
        int t = s_task;
        if (t >= TASK_TOTAL) return;

        // ---- decode task ----
        int task, gy, bx;
        if (t < TASK_PROD) {
            gy = t / 40; int c = t - gy * 40;
            if (c < 32) { task = TASK_ACT;  bx = c; }
            else        { task = TASK_GATE; bx = c - 32; }
        } else {
            int u = t - TASK_PROD;
            task = TASK_MIX; gy = u >> 3; bx = u & 7;
        }

        bool dom = gy >= 64;
        int e = 0, Mloc = NTOK, rowBase = 0, rowTile = 0;
        if (!dom) rowTile = gy * 128;
        else if (!dom_tile(gy - 64, e, Mloc, rowBase, rowTile)) continue;  // uniform

        const bf16 *A, *Wt;
        const float* bias;
        int K, Nd;
        if (task == TASK_ACT) {
            K = DIM; Nd = FFN;
            A    = dom ? g_Xgb + (size_t)rowBase * K : g_Xb;
            Wt   = dom ? g_dW1t + (size_t)e * K * Nd : g_sW1t;
            bias = dom ? db1 + (size_t)e * Nd : sb1;
        } else if (task == TASK_GATE) {
            K = DIM; Nd = DIM;
            A    = dom ? g_Xgb + (size_t)rowBase * K : g_Xb;
            Wt   = dom ? g_dWgt + (size_t)e * K * Nd : g_sWgt;
            bias = dom ? dbg + (size_t)e * Nd : sbg;
        } else {
            K = FFN; Nd = DIM;
            A    = (dom ? g_Ad : g_Ab) + (dom ? (size_t)rowBase * K : 0);
            Wt   = dom ? g_dW2t + (size_t)e * K * Nd : g_sW2t;
            bias = dom ? db2 + (size_t)e * Nd : sb2;
            // wait for this row-group's 32 act + 8 gate producers
            if (tid == 0) {
                volatile int* rc = g_rowCnt;
                while (rc[gy] < DEP_TARGET) __nanosleep(64);
            }
            __syncthreads();
            __threadfence();              // acquire: producers' stores now visible
        }

        int colTile = bx * 128;

        float acc[4][4][4];
#pragma unroll
        for (int mi = 0; mi < 4; mi++)
#pragma unroll
            for (int ni = 0; ni < 4; ni++)
#pragma unroll
                for (int j = 0; j < 4; j++) acc[mi][ni][j] = 0.f;

        const int chunks = K >> 6;

#define ISSUE(chunk, slot)                                                        \
        do {                                                                      \
            int _kk = (chunk) << 6;                                               \
            uint32_t _aO = asb + (uint32_t)(slot) * BUFBY;                        \
            uint32_t _bO = bsb + (uint32_t)(slot) * BUFBY;                        \
            _Pragma("unroll")                                                     \
            for (int _p = 0; _p < 4; _p++) {                                      \
                int _row = srow + _p * 32;                                        \
                int _av  = (rowTile + _row) < Mloc ? 16 : 0;                      \
                cp16(_aO + (uint32_t)(_row * ROWB + sseg * 2),                    \
                     A + (size_t)(rowTile + _row) * K + _kk + sseg, _av);         \
                cp16(_bO + (uint32_t)(_row * ROWB + sseg * 2),                    \
                     Wt + (size_t)(colTile + _row) * K + _kk + sseg, 16);         \
            }                                                                     \
            cp_commit();                                                          \
        } while (0)

        ISSUE(0, 0);
        ISSUE(1, 1);

        int sCur = 0;
        for (int i = 0; i < chunks; i++) {
            if (i + 1 < chunks) cp_wait<1>();
            else                cp_wait<0>();
            __syncthreads();
            if (i + 2 < chunks) {
                int slot = sCur + 2; if (slot >= STAGES) slot -= STAGES;
                ISSUE(i + 2, slot);
            }
            uint32_t aBuf = asb + (uint32_t)sCur * BUFBY;
            uint32_t bBuf = bsb + (uint32_t)sCur * BUFBY;
#pragma unroll
            for (int kb = 0; kb < 64; kb += 16) {
                uint32_t af[4][4], bfr[4][2];
#pragma unroll
                for (int mi = 0; mi < 4; mi++)
                    ldsm_x4(af[mi], aBuf + (uint32_t)((warpM * 64 + mi * 16) * ROWB + kb * 2 + aoffB));
#pragma unroll
                for (int ni = 0; ni < 4; ni++)
                    ldsm_x2(bfr[ni], bBuf + (uint32_t)((warpN * 32 + ni * 8) * ROWB + kb * 2 + boffB));
#pragma unroll
                for (int mi = 0; mi < 4; mi++)
#pragma unroll
                    for (int ni = 0; ni < 4; ni++)
                        mma_bf16(acc[mi][ni], af[mi], bfr[ni]);
            }
            if (++sCur == STAGES) sCur = 0;
        }
#undef ISSUE

        // ---- epilogue ----
#pragma unroll
        for (int mi = 0; mi < 4; mi++)
#pragma unroll
            for (int h = 0; h < 2; h++) {
                int lr = rowTile + warpM * 64 + mi * 16 + grp + h * 8;
                if (lr >= Mloc) continue;
                int grow = dom ? rowBase + lr : lr;
#pragma unroll
                for (int ni = 0; ni < 4; ni++) {
                    int col = colTile + warpN * 32 + ni * 8 + t4 * 2;
                    float v0 = acc[mi][ni][h * 2 + 0];
                    float v1 = acc[mi][ni][h * 2 + 1];
                    if (task == TASK_ACT) {
                        float a0 = v0 + bias[col];
                        float a1 = v1 + bias[col + 1];
                        a0 = 0.5f * a0 * (1.0f + erff(a0 * 0.70710678118654752f));
                        a1 = 0.5f * a1 * (1.0f + erff(a1 * 0.70710678118654752f));
                        union { __nv_bfloat162 h2; uint32_t u; } cv;
                        cv.h2 = __floats2bfloat162_rn(a0, a1);
                        *(uint32_t*)((dom ? g_Ad : g_Ab) + (size_t)grow * FFN + col) = cv.u;
                    } else if (task == TASK_GATE) {
                        float* dst = (dom ? g_Gd : g_G) + (size_t)grow * DIM + col;
                        dst[0] = 1.0f / (1.0f + expf(-(v0 + bias[col])));
                        dst[1] = 1.0f / (1.0f + expf(-(v1 + bias[col + 1])));
                    } else {
                        const float* xp = (dom ? g_Xg : xf) + (size_t)grow * DIM + col;
                        const float* gp = (dom ? g_Gd : g_G) + (size_t)grow * DIM + col;
                        float x0 = xp[0], x1 = xp[1];
                        float h0 = v0 + bias[col]     + x0;
                        float h1 = v1 + bias[col + 1] + x1;
                        float g0 = gp[0], g1 = gp[1];
                        float o0 = g0 * h0 + (1.0f - g0) * x0;
                        float o1 = g1 * h1 + (1.0f - g1) * x1;
                        float* dst = (dom ? g_Od + (size_t)grow * DIM
                                          : out + (size_t)grow * DIM) + col;
                        dst[0] = o0;
                        dst[1] = o1;
                    }
                }
            }

        // ---- producer release: signal row-group counter ----
        if (task != TASK_MIX) {
            __threadfence();              // make this CTA's stores visible
            __syncthreads();              // all threads' fences complete
            if (tid == 0) atomicAdd(&g_rowCnt[gy], 1);
        }
    }
}

// ---------------- launch -----------------------------------------------------
extern "C" void kernel_launch(void* const* d_in, const int* in_sizes, int n_in,
                              void* d_out, int out_size)
{
    const float* x   = (const float*)d_in[0];
    const int*   ids = (const int*)  d_in[1];
    const float* sW1 = (const float*)d_in[2];
    const float* sb1 = (const float*)d_in[3];
    const float* sW2 = (const float*)d_in[4];
    const float* sb2 = (const float*)d_in[5];
    const float* sWg = (const float*)d_in[6];
    const float* sbg = (const float*)d_in[7];
    const float* dW1 = (const float*)d_in[8];
    const float* db1 = (const float*)d_in[9];
    const float* dW2 = (const float*)d_in[10];
    const float* db2 = (const float*)d_in[11];
    const float* dWg = (const float*)d_in[12];
    const float* dbg = (const float*)d_in[13];
    float* out = (float*)d_out;

    cudaFuncSetAttribute(gemm_persist, cudaFuncAttributeMaxDynamicSharedMemorySize, SMEM_BYTES);

    // routing + converts
    k_zero     <<<1, 256>>>();
    k_count_cvt<<<NTOK * DIM / 4 / 256, 256>>>(ids, x);
    k_scan     <<<1, 32>>>();
    k_scatter  <<<NTOK / 256, 256>>>(ids);
    k_gather   <<<NTOK, 256>>>(x);

    // all weight transposes+converts in one launch
    k_transpose_all<<<101376, dim3(32, 8)>>>(sW1, sW2, sWg, dW1, dW2, dWg);

    // ONE persistent launch: GEMM1 acts + gate GEMMs + GEMM2/mix via task queue
    gemm_persist<<<304, 256, SMEM_BYTES>>>(x, sb1, db1, sbg, dbg, sb2, db2, out);

    // Combine: out[perm[p]] += domain mix
    k_combine<<<NTOK, 256>>>(out);
}